// round 7
// baseline (speedup 1.0000x reference)
#include <cuda_runtime.h>
#include <cstdint>

// YOLO post-process: (16, 25200, 85) fp32 -> (16, 25200, 6) fp32
//
// R6: R4 geometry (128 threads, 128-row/43.5KB tiles, depth-2 DMA pipeline,
//     2 blocks/SM) + coarse-grained atomic ticket scheduler (perfect balance)
//     + self-resetting counters (no extra reset launch, graph-replayable).

#define N_ROWS        403200          // 16 * 25200
#define N_CH          85
#define N_OUT         6
#define CONF_TH       0.25f
#define TILE_ROWS     128
#define NT            (N_ROWS / TILE_ROWS)   // 3150
#define DEPTH         2
#define BLOCK_THREADS 128
#define TILE_FLOATS   (TILE_ROWS * N_CH)     // 10880
#define TILE_BYTES    (TILE_FLOATS * 4)      // 43520
#define OUT_FLOATS    (TILE_ROWS * N_OUT)    // 768
#define OUT_VEC4      (OUT_FLOATS / 4)       // 192
#define GRID_BLOCKS   296                    // 2 per SM * 148

// dynamic smem layout:
//   [0,16)   mbar[2]
//   [16,24)  ticket queue tq[2]
//   [32,+2T) in bufs
//   then 2 out bufs (3072 B each)
#define SM_IN    32
#define SM_OUT   (SM_IN + DEPTH * TILE_BYTES)        // 87072
#define SM_TOTAL (SM_OUT + 2 * OUT_FLOATS * 4)       // 93216

__device__ unsigned g_ticket;   // statically zero; restored to 0 by last block each run
__device__ unsigned g_done;

__device__ __forceinline__ unsigned smem_u32(const void* p) {
    unsigned a;
    asm("{ .reg .u64 t; cvta.to.shared.u64 t, %1; cvt.u32.u64 %0, t; }"
        : "=r"(a) : "l"(p));
    return a;
}

__device__ __forceinline__ void mbar_init(unsigned addr, unsigned count) {
    asm volatile("mbarrier.init.shared.b64 [%0], %1;" :: "r"(addr), "r"(count) : "memory");
}

__device__ __forceinline__ void bulk_load(unsigned dst_smem, const void* gsrc,
                                          unsigned bytes, unsigned mbar) {
    asm volatile("mbarrier.arrive.expect_tx.shared.b64 _, [%0], %1;"
                 :: "r"(mbar), "r"(bytes) : "memory");
    asm volatile("cp.async.bulk.shared::cta.global.mbarrier::complete_tx::bytes "
                 "[%0], [%1], %2, [%3];"
                 :: "r"(dst_smem), "l"(gsrc), "r"(bytes), "r"(mbar) : "memory");
}

__device__ __forceinline__ void mbar_wait(unsigned addr, unsigned parity) {
    asm volatile(
        "{\n\t"
        ".reg .pred P;\n\t"
        "W%=:\n\t"
        "mbarrier.try_wait.parity.acquire.cta.shared::cta.b64 P, [%0], %1, 0x989680;\n\t"
        "@P bra D%=;\n\t"
        "bra W%=;\n\t"
        "D%=:\n\t"
        "}"
        :: "r"(addr), "r"(parity) : "memory");
}

__global__ __launch_bounds__(BLOCK_THREADS, 2)
void yolo_post_kernel(const float* __restrict__ in, float4* __restrict__ out4)
{
    extern __shared__ char sb[];
    const unsigned base = smem_u32(sb);
    int* const tq = reinterpret_cast<int*>(sb + 16);
    float* const in_base  = reinterpret_cast<float*>(sb + SM_IN);
    float* const out_base = reinterpret_cast<float*>(sb + SM_OUT);

    const int tid = threadIdx.x;

    if (tid == 0) {
        mbar_init(base + 0, 1);
        mbar_init(base + 8, 1);
        // Prologue: fetch first ticket, launch its DMA into slot 0.
        int t = (int)atomicAdd(&g_ticket, 1u);
        tq[0] = t;
        if (t < NT) {
            bulk_load(base + SM_IN, in + (size_t)t * TILE_FLOATS, TILE_BYTES, base + 0);
        }
    }
    __syncthreads();

    for (int it = 0; ; ++it) {
        const int slot   = it & 1;
        const int slot_w = (it + 1) & 1;

        // Fetch next ticket & issue its DMA into the buffer freed last iteration
        // (all LDS reads of it completed before the previous __syncthreads).
        if (tid == 0) {
            int t = (int)atomicAdd(&g_ticket, 1u);
            tq[slot_w] = t;
            if (t < NT) {
                bulk_load(base + SM_IN + slot_w * TILE_BYTES,
                          in + (size_t)t * TILE_FLOATS, TILE_BYTES,
                          base + slot_w * 8);
            }
        }

        const int tile = tq[slot];   // written last iteration (or prologue), synced
        if (tile >= NT) break;       // tickets monotone: no valid DMA remains pending

        mbar_wait(base + slot * 8, (unsigned)((it >> 1) & 1));

        // ---- compute: thread-per-row (stride-85 LDS = conflict-free) ----
        const float* row = in_base + slot * TILE_FLOATS + tid * N_CH;

        const float x    = row[0];
        const float y    = row[1];
        const float w    = row[2];
        const float h    = row[3];
        const float conf = row[4];

        float b0 = row[5 +  0], b1 = row[5 + 20], b2 = row[5 + 40], b3 = row[5 + 60];
        int   i0 = 0,           i1 = 20,          i2 = 40,          i3 = 60;

        #pragma unroll
        for (int c = 1; c < 20; c++) {
            float v0 = row[5 +  0 + c];
            float v1 = row[5 + 20 + c];
            float v2 = row[5 + 40 + c];
            float v3 = row[5 + 60 + c];
            if (v0 > b0) { b0 = v0; i0 =  0 + c; }
            if (v1 > b1) { b1 = v1; i1 = 20 + c; }
            if (v2 > b2) { b2 = v2; i2 = 40 + c; }
            if (v3 > b3) { b3 = v3; i3 = 60 + c; }
        }
        // Ordered merge: ties keep the earlier quarter -> first-index semantics.
        if (b1 > b0) { b0 = b1; i0 = i1; }
        if (b2 > b0) { b0 = b2; i0 = i2; }
        if (b3 > b0) { b0 = b3; i0 = i3; }

        const float score = conf * b0;
        const bool  pass  = score > CONF_TH;
        const float hw = 0.5f * w;
        const float hh = 0.5f * h;

        float o0 = 0.f, o1 = 0.f, o2 = 0.f, o3 = 0.f, o4 = 0.f, o5 = 0.f;
        if (pass) {
            o0 = x - hw;
            o1 = y - hh;
            o2 = x + hw;
            o3 = y + hh;
            o4 = score;
            o5 = (float)i0;
        }

        // ---- stage outputs (alternating buffer), coalesced float4 store ----
        float* ob = out_base + (it & 1) * OUT_FLOATS;
        float* so = ob + tid * N_OUT;
        so[0] = o0; so[1] = o1; so[2] = o2; so[3] = o3; so[4] = o4; so[5] = o5;
        __syncthreads();   // LDS reads of in-buf done (DMA reuse safe) + staging visible

        {
            const float4* src = reinterpret_cast<const float4*>(ob);
            float4* dst = out4 + (size_t)tile * OUT_VEC4;
            #pragma unroll
            for (int i = tid; i < OUT_VEC4; i += BLOCK_THREADS)
                dst[i] = src[i];
        }
    }

    // Self-reset: last block to finish restores counters for the next run
    // (graph replays re-enter with g_ticket == 0, g_done == 0).
    if (tid == 0) {
        __threadfence();
        unsigned d = atomicAdd(&g_done, 1u);
        if (d == GRID_BLOCKS - 1) {
            g_ticket = 0u;
            g_done   = 0u;
            __threadfence();
        }
    }
}

extern "C" void kernel_launch(void* const* d_in, const int* in_sizes, int n_in,
                              void* d_out, int out_size)
{
    const float* in  = (const float*)d_in[0];
    float4*      out = (float4*)d_out;
    cudaFuncSetAttribute(yolo_post_kernel,
                         cudaFuncAttributeMaxDynamicSharedMemorySize, SM_TOTAL);
    yolo_post_kernel<<<GRID_BLOCKS, BLOCK_THREADS, SM_TOTAL>>>(in, out);
}

// round 8
// speedup vs baseline: 1.0850x; 1.0850x over previous
#include <cuda_runtime.h>
#include <cstdint>

// YOLO post-process: (16, 25200, 85) fp32 -> (16, 25200, 6) fp32
//
// R7: R4 pipeline (depth-2 cp.async.bulk, 128 threads, issue-before-wait,
//     zero global coordination) + static contiguous near-balanced chunks:
//     each block owns a contiguous row range (multiple of 4 rows => every
//     bulk-copy source is 16B-aligned), sizes 1364/1360 rows (0.3% skew).

#define N_ROWS        403200          // 16 * 25200
#define N_CH          85
#define N_OUT         6
#define CONF_TH       0.25f
#define TILE_ROWS     128
#define BLOCK_THREADS 128
#define TILE_FLOATS   (TILE_ROWS * N_CH)     // 10880
#define TILE_BYTES    (TILE_FLOATS * 4)      // 43520
#define OUT_FLOATS    (TILE_ROWS * N_OUT)    // 768
#define GRID_BLOCKS   296                    // 2 per SM * 148

// Chunking in quad-rows (4 rows = 1360 B, 16B-aligned steps):
//   total quads = 100800 = 296*340 + 160  -> first 160 blocks get 341 quads.
#define QUADS_BASE    340
#define QUADS_EXTRA   160

// dynamic smem layout:
//   [0,16)   mbar[2]
//   [32,+2T) in bufs
//   then 2 out bufs (3072 B each)
#define SM_IN    32
#define SM_OUT   (SM_IN + 2 * TILE_BYTES)            // 87072
#define SM_TOTAL (SM_OUT + 2 * OUT_FLOATS * 4)       // 93216

__device__ __forceinline__ unsigned smem_u32(const void* p) {
    unsigned a;
    asm("{ .reg .u64 t; cvta.to.shared.u64 t, %1; cvt.u32.u64 %0, t; }"
        : "=r"(a) : "l"(p));
    return a;
}

__device__ __forceinline__ void mbar_init(unsigned addr, unsigned count) {
    asm volatile("mbarrier.init.shared.b64 [%0], %1;" :: "r"(addr), "r"(count) : "memory");
}

__device__ __forceinline__ void bulk_load(unsigned dst_smem, const void* gsrc,
                                          unsigned bytes, unsigned mbar) {
    asm volatile("mbarrier.arrive.expect_tx.shared.b64 _, [%0], %1;"
                 :: "r"(mbar), "r"(bytes) : "memory");
    asm volatile("cp.async.bulk.shared::cta.global.mbarrier::complete_tx::bytes "
                 "[%0], [%1], %2, [%3];"
                 :: "r"(dst_smem), "l"(gsrc), "r"(bytes), "r"(mbar) : "memory");
}

__device__ __forceinline__ void mbar_wait(unsigned addr, unsigned parity) {
    asm volatile(
        "{\n\t"
        ".reg .pred P;\n\t"
        "W%=:\n\t"
        "mbarrier.try_wait.parity.acquire.cta.shared::cta.b64 P, [%0], %1, 0x989680;\n\t"
        "@P bra D%=;\n\t"
        "bra W%=;\n\t"
        "D%=:\n\t"
        "}"
        :: "r"(addr), "r"(parity) : "memory");
}

__global__ __launch_bounds__(BLOCK_THREADS, 2)
void yolo_post_kernel(const float* __restrict__ in, float4* __restrict__ out4)
{
    extern __shared__ char sb[];
    const unsigned base = smem_u32(sb);
    float* const in_base  = reinterpret_cast<float*>(sb + SM_IN);
    float* const out_base = reinterpret_cast<float*>(sb + SM_OUT);

    const int tid = threadIdx.x;
    const int b   = blockIdx.x;

    // Contiguous chunk for this block (quad-row granularity).
    const int q_start = QUADS_BASE * b + (b < QUADS_EXTRA ? b : QUADS_EXTRA);
    const int row0    = 4 * q_start;
    const int n_rows  = 4 * (QUADS_BASE + (b < QUADS_EXTRA ? 1 : 0));   // 1364 or 1360
    const int n_tiles = (n_rows + TILE_ROWS - 1) / TILE_ROWS;           // 11

    if (tid == 0) {
        mbar_init(base + 0, 1);
        mbar_init(base + 8, 1);
        // Prologue: issue DMA for tile 0 into slot 0.
        const int tr0 = (n_rows < TILE_ROWS) ? n_rows : TILE_ROWS;
        bulk_load(base + SM_IN, in + (size_t)row0 * N_CH,
                  (unsigned)(tr0 * N_CH * 4), base + 0);
    }
    __syncthreads();

    for (int it = 0; it < n_tiles; ++it) {
        const int slot   = it & 1;
        const int slot_w = (it + 1) & 1;

        // Issue DMA for the next tile into the buffer freed last iteration.
        if (tid == 0 && it + 1 < n_tiles) {
            const int r_off = (it + 1) * TILE_ROWS;
            int tr = n_rows - r_off;
            if (tr > TILE_ROWS) tr = TILE_ROWS;
            bulk_load(base + SM_IN + slot_w * TILE_BYTES,
                      in + (size_t)(row0 + r_off) * N_CH,
                      (unsigned)(tr * N_CH * 4), base + slot_w * 8);
        }

        // Wait for current tile.
        mbar_wait(base + slot * 8, (unsigned)((it >> 1) & 1));

        const int r_off     = it * TILE_ROWS;
        int tile_rows = n_rows - r_off;
        if (tile_rows > TILE_ROWS) tile_rows = TILE_ROWS;

        // ---- compute: thread-per-row (stride-85 LDS = conflict-free) ----
        float* ob = out_base + (it & 1) * OUT_FLOATS;
        if (tid < tile_rows) {
            const float* row = in_base + slot * TILE_FLOATS + tid * N_CH;

            const float x    = row[0];
            const float y    = row[1];
            const float w    = row[2];
            const float h    = row[3];
            const float conf = row[4];

            float b0 = row[5 +  0], b1 = row[5 + 20], b2 = row[5 + 40], b3 = row[5 + 60];
            int   i0 = 0,           i1 = 20,          i2 = 40,          i3 = 60;

            #pragma unroll
            for (int c = 1; c < 20; c++) {
                float v0 = row[5 +  0 + c];
                float v1 = row[5 + 20 + c];
                float v2 = row[5 + 40 + c];
                float v3 = row[5 + 60 + c];
                if (v0 > b0) { b0 = v0; i0 =  0 + c; }
                if (v1 > b1) { b1 = v1; i1 = 20 + c; }
                if (v2 > b2) { b2 = v2; i2 = 40 + c; }
                if (v3 > b3) { b3 = v3; i3 = 60 + c; }
            }
            // Ordered merge: ties keep the earlier quarter -> first-index semantics.
            if (b1 > b0) { b0 = b1; i0 = i1; }
            if (b2 > b0) { b0 = b2; i0 = i2; }
            if (b3 > b0) { b0 = b3; i0 = i3; }

            const float score = conf * b0;
            const bool  pass  = score > CONF_TH;
            const float hw = 0.5f * w;
            const float hh = 0.5f * h;

            float o0 = 0.f, o1 = 0.f, o2 = 0.f, o3 = 0.f, o4 = 0.f, o5 = 0.f;
            if (pass) {
                o0 = x - hw;
                o1 = y - hh;
                o2 = x + hw;
                o3 = y + hh;
                o4 = score;
                o5 = (float)i0;
            }

            float* so = ob + tid * N_OUT;
            so[0] = o0; so[1] = o1; so[2] = o2; so[3] = o3; so[4] = o4; so[5] = o5;
        }
        __syncthreads();   // LDS reads of in-buf done (DMA reuse safe) + staging visible

        // ---- coalesced float4 store (tile_rows*6 floats, divisible by 4: rows%4==0) ----
        {
            const int nvec = (tile_rows * N_OUT) / 4;
            const float4* src = reinterpret_cast<const float4*>(ob);
            float4* dst = reinterpret_cast<float4*>(
                reinterpret_cast<float*>(out4) + (size_t)(row0 + r_off) * N_OUT);
            for (int i = tid; i < nvec; i += BLOCK_THREADS)
                dst[i] = src[i];
        }
    }
}

extern "C" void kernel_launch(void* const* d_in, const int* in_sizes, int n_in,
                              void* d_out, int out_size)
{
    const float* in  = (const float*)d_in[0];
    float4*      out = (float4*)d_out;
    cudaFuncSetAttribute(yolo_post_kernel,
                         cudaFuncAttributeMaxDynamicSharedMemorySize, SM_TOTAL);
    yolo_post_kernel<<<GRID_BLOCKS, BLOCK_THREADS, SM_TOTAL>>>(in, out);
}